// round 1
// baseline (speedup 1.0000x reference)
#include <cuda_runtime.h>
#include <cuda_bf16.h>
#include <math_constants.h>

// ---------------- problem constants ----------------
#define BATCH   32
#define Q_LEN   32
#define HID     128
#define DOC_LEN 128
#define K_CAND  256
#define K_OUT   16
#define N_PIDS  20000
#define N_EMB   (N_PIDS * DOC_LEN)   // 2,560,000

// doc tile smem pitch in floats (multiple of 4 for 16B alignment; 132%32=4
// gives conflict-free STS.128 stores and conflict-free LDS.128 loads)
#define DPITCH  132

// ---------------- device scratch (no allocations allowed) ----------------
__device__ int   g_is64;
__device__ int   g_upids[BATCH * K_CAND];
__device__ int   g_ucnt[BATCH];
__device__ float g_scores[BATCH * K_CAND];

// ---------------- f32x2 packed-FMA helpers (Blackwell) ----------------
__device__ __forceinline__ unsigned long long f2pack(float x, float y) {
    unsigned long long r;
    asm("mov.b64 %0, {%1, %2};" : "=l"(r) : "f"(x), "f"(y));
    return r;
}
__device__ __forceinline__ float2 f2unpack(unsigned long long u) {
    float2 f;
    asm("mov.b64 {%0, %1}, %2;" : "=f"(f.x), "=f"(f.y) : "l"(u));
    return f;
}
__device__ __forceinline__ unsigned long long ffma2(unsigned long long a,
                                                    unsigned long long b,
                                                    unsigned long long c) {
    unsigned long long d;
    asm("fma.rn.f32x2 %0, %1, %2, %3;" : "=l"(d) : "l"(a), "l"(b), "l"(c));
    return d;
}

// ---------------- kernel 0: detect index dtype ----------------
// If topk_indices is int64, every 8-byte word is a valid index in [0, N_EMB).
// If it is int32, reading as int64 combines two indices -> huge values.
// Reading 4096 int64 = 32 KB, safe for both layouts (int32 buffer is 32 KB).
__global__ void detect_kernel(const void* idx_raw) {
    __shared__ int ok;
    if (threadIdx.x == 0) ok = 1;
    __syncthreads();
    const long long* p = (const long long*)idx_raw;
    bool good = true;
    for (int i = threadIdx.x; i < (BATCH * K_CAND) / 2; i += blockDim.x) {
        long long v = p[i];
        if (v < 0 || v >= (long long)N_EMB) good = false;
    }
    if (!good) atomicAnd(&ok, 0);
    __syncthreads();
    if (threadIdx.x == 0) g_is64 = ok;
}

// ---------------- kernel 1: per-row dedup (sorted unique pids) ----------------
__global__ void dedup_kernel(const void* idx_raw) {
    const int b = blockIdx.x;
    const int t = threadIdx.x;
    __shared__ int pids[K_CAND];
    __shared__ int wsum[8];

    long long v;
    if (g_is64) v = ((const long long*)idx_raw)[b * K_CAND + t];
    else        v = (long long)(((const int*)idx_raw)[b * K_CAND + t]);
    pids[t] = (int)(v >> 7);   // emb2pid[i] == i / DOC_LEN, DOC_LEN = 128
    __syncthreads();

    // bitonic sort ascending (256 elements, 256 threads)
    for (int k = 2; k <= K_CAND; k <<= 1) {
        for (int j = k >> 1; j > 0; j >>= 1) {
            int ixj = t ^ j;
            if (ixj > t) {
                int a = pids[t], c = pids[ixj];
                bool up = ((t & k) == 0);
                if ((a > c) == up) { pids[t] = c; pids[ixj] = a; }
            }
            __syncthreads();
        }
    }

    int myv  = pids[t];
    int flag = (t == 0) || (myv != pids[t - 1]);

    // stable stream-compaction (exclusive scan of flags)
    unsigned mask = __ballot_sync(0xffffffffu, flag);
    int lane = t & 31, w = t >> 5;
    int pre  = __popc(mask & ((1u << lane) - 1));
    if (lane == 31) wsum[w] = pre + flag;
    __syncthreads();
    int base = 0;
    for (int i = 0; i < w; i++) base += wsum[i];
    int pos = base + pre;
    if (flag) g_upids[b * K_CAND + pos] = myv;
    if (t == K_CAND - 1) g_ucnt[b] = pos + flag;
}

// ---------------- kernel 2: scoring ----------------
// One CTA per (batch, candidate slot). 128 threads.
// Thread tile: 8 q-rows (by warp) x 4 d-cols (dg, dg+32, dg+64, dg+96).
__global__ void score_kernel(const float* __restrict__ qv,
                             const float* __restrict__ vectors) {
    extern __shared__ float sm[];
    float* ds = sm;                          // [DOC_LEN][DPITCH]
    float* qs = sm + DOC_LEN * DPITCH;       // [Q_LEN][HID]
    __shared__ float wq[4];

    const int b    = blockIdx.y;
    const int slot = blockIdx.x;
    const int tid  = threadIdx.x;
    const int cnt  = g_ucnt[b];

    if (slot >= cnt) {
        if (tid == 0) g_scores[b * K_CAND + slot] = -CUDART_INF_F;
        return;
    }
    const int pid = g_upids[b * K_CAND + slot];

    // stage q [32x128] (16 KB), coalesced float4
    const float4* q4 = (const float4*)(qv + (size_t)b * Q_LEN * HID);
    for (int i = tid; i < (Q_LEN * HID) / 4; i += 128)
        ((float4*)qs)[i] = q4[i];

    // stage doc tile [128x128] (64 KB) into pitch-132 smem, conflict-free STS.128
    const float4* d4 = (const float4*)(vectors + (size_t)pid * DOC_LEN * HID);
    for (int i = tid; i < (DOC_LEN * HID) / 4; i += 128) {
        int d  = i >> 5;         // 32 float4 per row
        int h4 = i & 31;
        *(float4*)(ds + d * DPITCH + h4 * 4) = d4[i];
    }
    __syncthreads();

    const int qg = tid >> 5;     // warp id -> q group (8 rows)
    const int dg = tid & 31;     // lane    -> d base
    const int q0 = qg * 8;

    unsigned long long acc[8][4];
#pragma unroll
    for (int j = 0; j < 8; j++)
#pragma unroll
        for (int m = 0; m < 4; m++) acc[j][m] = 0ull;

#pragma unroll 2
    for (int k2 = 0; k2 < HID / 2; k2 += 2) {
        unsigned long long qA[8], qB[8];
#pragma unroll
        for (int j = 0; j < 8; j++) {
            float4 v = *(const float4*)(qs + (q0 + j) * HID + 2 * k2);  // broadcast
            qA[j] = f2pack(v.x, v.y);
            qB[j] = f2pack(v.z, v.w);
        }
        unsigned long long dA[4], dB[4];
#pragma unroll
        for (int m = 0; m < 4; m++) {
            float4 v = *(const float4*)(ds + (dg + 32 * m) * DPITCH + 2 * k2);
            dA[m] = f2pack(v.x, v.y);
            dB[m] = f2pack(v.z, v.w);
        }
#pragma unroll
        for (int j = 0; j < 8; j++)
#pragma unroll
            for (int m = 0; m < 4; m++) {
                acc[j][m] = ffma2(dA[m], qA[j], acc[j][m]);
                acc[j][m] = ffma2(dB[m], qB[j], acc[j][m]);
            }
    }

    // per-q max over this thread's 4 d, then over the warp's 128 d
    float sum8 = 0.0f;
#pragma unroll
    for (int j = 0; j < 8; j++) {
        float mx = -CUDART_INF_F;
#pragma unroll
        for (int m = 0; m < 4; m++) {
            float2 f = f2unpack(acc[j][m]);
            mx = fmaxf(mx, f.x + f.y);
        }
#pragma unroll
        for (int o = 16; o > 0; o >>= 1)
            mx = fmaxf(mx, __shfl_xor_sync(0xffffffffu, mx, o));
        sum8 += mx;
    }
    if (dg == 0) wq[qg] = sum8;
    __syncthreads();
    if (tid == 0)
        g_scores[b * K_CAND + slot] =
            (wq[0] + wq[1] + wq[2] + wq[3]) * (1.0f / (float)Q_LEN);
}

// ---------------- kernel 3: top-16 selection + output ----------------
__global__ void topk_kernel(float* __restrict__ out, int out_size) {
    const int b = blockIdx.x;
    const int t = threadIdx.x;
    __shared__ float sc[K_CAND];
    __shared__ float rs[K_CAND];
    __shared__ int   ri[K_CAND];

    sc[t] = g_scores[b * K_CAND + t];
    __syncthreads();

    const bool both = (out_size >= BATCH * K_OUT * 2);
    for (int it = 0; it < K_OUT; it++) {
        rs[t] = sc[t];
        ri[t] = t;
        __syncthreads();
        for (int s = 128; s > 0; s >>= 1) {
            if (t < s) {
                float a = rs[t], c = rs[t + s];
                if (c > a || (c == a && ri[t + s] < ri[t])) {   // lower index wins ties
                    rs[t] = c; ri[t] = ri[t + s];
                }
            }
            __syncthreads();
        }
        if (t == 0) {
            int best = ri[0];
            out[b * K_OUT + it] = (float)g_upids[b * K_CAND + best];
            if (both) out[BATCH * K_OUT + b * K_OUT + it] = rs[0];
            sc[best] = -CUDART_INF_F;
        }
        __syncthreads();
    }
}

// ---------------- launcher ----------------
extern "C" void kernel_launch(void* const* d_in, const int* in_sizes, int n_in,
                              void* d_out, int out_size) {
    // locate inputs by element count (robust to ordering / scalar-k presence)
    int qi = 0, ii = 1, vi = 3;
    for (int i = 0; i < n_in; i++) {
        if (in_sizes[i] == BATCH * Q_LEN * HID)                 qi = i;
        else if (in_sizes[i] == BATCH * K_CAND)                 ii = i;
        else if (in_sizes[i] == N_PIDS * DOC_LEN * HID)         vi = i;
    }
    const float* q       = (const float*)d_in[qi];
    const void*  idx     = d_in[ii];
    const float* vectors = (const float*)d_in[vi];

    detect_kernel<<<1, 256>>>(idx);
    dedup_kernel<<<BATCH, K_CAND>>>(idx);

    size_t smem = (size_t)(DOC_LEN * DPITCH + Q_LEN * HID) * sizeof(float); // ~84 KB
    cudaFuncSetAttribute(score_kernel,
                         cudaFuncAttributeMaxDynamicSharedMemorySize, (int)smem);
    dim3 grid(K_CAND, BATCH);
    score_kernel<<<grid, 128, smem>>>(q, vectors);

    topk_kernel<<<BATCH, K_CAND>>>((float*)d_out, out_size);
}

// round 2
// speedup vs baseline: 1.4434x; 1.4434x over previous
#include <cuda_runtime.h>
#include <cuda_bf16.h>
#include <math_constants.h>

// ---------------- problem constants ----------------
#define BATCH   32
#define Q_LEN   32
#define HID     128
#define DOC_LEN 128
#define K_CAND  256
#define K_OUT   16
#define N_PIDS  20000
#define N_EMB   (N_PIDS * DOC_LEN)   // 2,560,000

// doc tile smem pitch in floats: stride 132 -> bank stride 4 -> conflict-free
// LDS.128 for lane-strided row reads, and 16B-aligned (132*4 % 16 == 0).
#define DPITCH  132

// ---------------- device scratch (no allocations allowed) ----------------
__device__ int   g_upids[BATCH * K_CAND];
__device__ int   g_ucnt[BATCH];
__device__ float g_scores[BATCH * K_CAND];

// ---------------- f32x2 packed-FMA helpers (Blackwell FFMA2) ----------------
__device__ __forceinline__ unsigned long long f2pack(float x, float y) {
    unsigned long long r;
    asm("mov.b64 %0, {%1, %2};" : "=l"(r) : "f"(x), "f"(y));
    return r;
}
__device__ __forceinline__ float2 f2unpack(unsigned long long u) {
    float2 f;
    asm("mov.b64 {%0, %1}, %2;" : "=f"(f.x), "=f"(f.y) : "l"(u));
    return f;
}
__device__ __forceinline__ unsigned long long ffma2(unsigned long long a,
                                                    unsigned long long b,
                                                    unsigned long long c) {
    unsigned long long d;
    asm("fma.rn.f32x2 %0, %1, %2, %3;" : "=l"(d) : "l"(a), "l"(b), "l"(c));
    return d;
}

// ---------------- cp.async helpers ----------------
__device__ __forceinline__ void cp16(void* smem_dst, const void* gsrc) {
    unsigned s = (unsigned)__cvta_generic_to_shared(smem_dst);
    asm volatile("cp.async.cg.shared.global [%0], [%1], 16;\n" :: "r"(s), "l"(gsrc));
}
__device__ __forceinline__ void cp_commit_wait_all() {
    asm volatile("cp.async.commit_group;\n" ::);
    asm volatile("cp.async.wait_group 0;\n" ::);
}

// ---------------- kernel 1: per-row dedup (sorted unique pids) -------------
// dtype detect fused per block: reads 128 int64 words (in-bounds for both the
// int32 [32KB] and int64 [64KB] layouts); int32 data read as int64 yields
// values >= 2^32 (top half = another nonzero index), so all-valid => int64.
__global__ void dedup_kernel(const void* idx_raw) {
    const int b = blockIdx.x;
    const int t = threadIdx.x;
    __shared__ int pids[K_CAND];
    __shared__ int wsum[8];
    __shared__ int s_ok;

    if (t == 0) s_ok = 1;
    __syncthreads();
    if (t < 128) {
        long long v = ((const long long*)idx_raw)[b * 128 + t];
        if (v < 0 || v >= (long long)N_EMB) atomicAnd(&s_ok, 0);
    }
    __syncthreads();
    const int is64 = s_ok;

    long long v;
    if (is64) v = ((const long long*)idx_raw)[b * K_CAND + t];
    else      v = (long long)(((const int*)idx_raw)[b * K_CAND + t]);
    pids[t] = (int)(v >> 7);   // emb2pid[i] == i / DOC_LEN, DOC_LEN = 128
    __syncthreads();

    // bitonic sort ascending (256 elements, 256 threads)
    for (int k = 2; k <= K_CAND; k <<= 1) {
        for (int j = k >> 1; j > 0; j >>= 1) {
            int ixj = t ^ j;
            if (ixj > t) {
                int a = pids[t], c = pids[ixj];
                bool up = ((t & k) == 0);
                if ((a > c) == up) { pids[t] = c; pids[ixj] = a; }
            }
            __syncthreads();
        }
    }

    int myv  = pids[t];
    int flag = (t == 0) || (myv != pids[t - 1]);

    unsigned mask = __ballot_sync(0xffffffffu, flag);
    int lane = t & 31, w = t >> 5;
    int pre  = __popc(mask & ((1u << lane) - 1));
    if (lane == 31) wsum[w] = pre + flag;
    __syncthreads();
    int base = 0;
    for (int i = 0; i < w; i++) base += wsum[i];
    int pos = base + pre;
    if (flag) g_upids[b * K_CAND + pos] = myv;
    if (t == K_CAND - 1) g_ucnt[b] = pos + flag;
}

// ---------------- kernel 2: scoring ----------------
// One CTA per (batch, candidate slot). 128 threads, 3 CTAs/SM (67.6KB smem).
// Doc tile in smem (lane-spread LDS.128); q read via uniform __ldg (L1-hot,
// keeps it OFF the shared-memory crossbar -> inner loop is FMA-issue bound).
__global__ void __launch_bounds__(128, 3)
score_kernel(const float* __restrict__ qv, const float* __restrict__ vectors) {
    extern __shared__ float ds[];            // [DOC_LEN][DPITCH]
    __shared__ float wq[4];

    const int b    = blockIdx.y;
    const int slot = blockIdx.x;
    const int tid  = threadIdx.x;
    const int cnt  = g_ucnt[b];

    if (slot >= cnt) {
        if (tid == 0) g_scores[b * K_CAND + slot] = -CUDART_INF_F;
        return;
    }
    const int pid = g_upids[b * K_CAND + slot];

    // stage doc tile [128x128] (64 KB) via cp.async into pitch-132 smem
    const float4* d4 = (const float4*)(vectors + (size_t)pid * DOC_LEN * HID);
#pragma unroll
    for (int r = 0; r < 32; r++) {
        int i  = r * 128 + tid;
        int d  = i >> 5;                 // 32 float4 per row
        int h4 = i & 31;
        cp16(ds + d * DPITCH + h4 * 4, d4 + i);
    }
    cp_commit_wait_all();
    __syncthreads();

    const int qg = tid >> 5;     // warp id -> q group (8 rows)
    const int dg = tid & 31;     // lane    -> d base
    const float* qb = qv + (size_t)b * Q_LEN * HID + (qg * 8) * HID;

    unsigned long long acc[8][4];
#pragma unroll
    for (int j = 0; j < 8; j++)
#pragma unroll
        for (int m = 0; m < 4; m++) acc[j][m] = 0ull;

#pragma unroll 4
    for (int k = 0; k < HID; k += 4) {
        unsigned long long qA[8], qB[8];
#pragma unroll
        for (int j = 0; j < 8; j++) {
            float4 v = __ldg((const float4*)(qb + j * HID + k));  // warp-uniform
            qA[j] = f2pack(v.x, v.y);
            qB[j] = f2pack(v.z, v.w);
        }
        unsigned long long dA[4], dB[4];
#pragma unroll
        for (int m = 0; m < 4; m++) {
            float4 v = *(const float4*)(ds + (dg + 32 * m) * DPITCH + k);
            dA[m] = f2pack(v.x, v.y);
            dB[m] = f2pack(v.z, v.w);
        }
#pragma unroll
        for (int j = 0; j < 8; j++)
#pragma unroll
            for (int m = 0; m < 4; m++) {
                acc[j][m] = ffma2(dA[m], qA[j], acc[j][m]);
                acc[j][m] = ffma2(dB[m], qB[j], acc[j][m]);
            }
    }

    // per-q max over this thread's 4 d, then over the warp's 128 d
    float sum8 = 0.0f;
#pragma unroll
    for (int j = 0; j < 8; j++) {
        float mx = -CUDART_INF_F;
#pragma unroll
        for (int m = 0; m < 4; m++) {
            float2 f = f2unpack(acc[j][m]);
            mx = fmaxf(mx, f.x + f.y);
        }
#pragma unroll
        for (int o = 16; o > 0; o >>= 1)
            mx = fmaxf(mx, __shfl_xor_sync(0xffffffffu, mx, o));
        sum8 += mx;
    }
    if (dg == 0) wq[qg] = sum8;
    __syncthreads();
    if (tid == 0)
        g_scores[b * K_CAND + slot] =
            (wq[0] + wq[1] + wq[2] + wq[3]) * (1.0f / (float)Q_LEN);
}

// ---------------- kernel 3: warp-per-batch top-16 (shuffle-only) -----------
__global__ void topk_kernel(float* __restrict__ out, int out_size) {
    const int b    = blockIdx.x;
    const int lane = threadIdx.x;   // 32 threads

    float v[8];
    int   sl[8];
#pragma unroll
    for (int i = 0; i < 8; i++) {
        int s = i * 32 + lane;                      // coalesced
        v[i]  = g_scores[b * K_CAND + s];
        sl[i] = s;
    }
    const bool both = (out_size >= BATCH * K_OUT * 2);

    for (int it = 0; it < K_OUT; it++) {
        float bv = -CUDART_INF_F;
        int   bs = 1 << 30;
#pragma unroll
        for (int i = 0; i < 8; i++)
            if (v[i] > bv || (v[i] == bv && sl[i] < bs)) { bv = v[i]; bs = sl[i]; }
#pragma unroll
        for (int o = 16; o > 0; o >>= 1) {
            float ov = __shfl_xor_sync(0xffffffffu, bv, o);
            int   os = __shfl_xor_sync(0xffffffffu, bs, o);
            if (ov > bv || (ov == bv && os < bs)) { bv = ov; bs = os; }
        }
        // all lanes agree after xor-butterfly
        if (lane == 0) {
            out[b * K_OUT + it] = (float)g_upids[b * K_CAND + bs];
            if (both) out[BATCH * K_OUT + b * K_OUT + it] = bv;
        }
        if ((bs & 31) == lane) v[bs >> 5] = -CUDART_INF_F;  // invalidate winner
    }
}

// ---------------- launcher ----------------
extern "C" void kernel_launch(void* const* d_in, const int* in_sizes, int n_in,
                              void* d_out, int out_size) {
    int qi = 0, ii = 1, vi = 3;
    for (int i = 0; i < n_in; i++) {
        if (in_sizes[i] == BATCH * Q_LEN * HID)            qi = i;
        else if (in_sizes[i] == BATCH * K_CAND)            ii = i;
        else if (in_sizes[i] == N_PIDS * DOC_LEN * HID)    vi = i;
    }
    const float* q       = (const float*)d_in[qi];
    const void*  idx     = d_in[ii];
    const float* vectors = (const float*)d_in[vi];

    dedup_kernel<<<BATCH, K_CAND>>>(idx);

    size_t smem = (size_t)(DOC_LEN * DPITCH) * sizeof(float);   // 67,584 B
    cudaFuncSetAttribute(score_kernel,
                         cudaFuncAttributeMaxDynamicSharedMemorySize, (int)smem);
    dim3 grid(K_CAND, BATCH);
    score_kernel<<<grid, 128, smem>>>(q, vectors);

    topk_kernel<<<BATCH, 32>>>((float*)d_out, out_size);
}

// round 3
// speedup vs baseline: 1.5010x; 1.0399x over previous
#include <cuda_runtime.h>
#include <cuda_bf16.h>
#include <math_constants.h>

// ---------------- problem constants ----------------
#define BATCH   32
#define Q_LEN   32
#define HID     128
#define DOC_LEN 128
#define K_CAND  256
#define K_OUT   16
#define N_PIDS  20000
#define N_EMB   (N_PIDS * DOC_LEN)   // 2,560,000

// doc tile smem pitch in floats: 132*4 = 528 B row stride (16B aligned),
// bank stride 4 -> conflict-free LDS.128 for lane-strided row reads.
#define DPITCH  132

// ---------------- device scratch (no allocations allowed) ----------------
__device__ int   g_upids[BATCH * K_CAND];
__device__ int   g_ucnt[BATCH];
__device__ float g_scores[BATCH * K_CAND];

typedef unsigned long long u64;

// ---------------- f32x2 helpers (Blackwell FFMA2) ----------------
__device__ __forceinline__ float2 f2unpack(u64 u) {
    float2 f;
    asm("mov.b64 {%0, %1}, %2;" : "=f"(f.x), "=f"(f.y) : "l"(u));
    return f;
}
__device__ __forceinline__ u64 ffma2(u64 a, u64 b, u64 c) {
    u64 d;
    asm("fma.rn.f32x2 %0, %1, %2, %3;" : "=l"(d) : "l"(a), "l"(b), "l"(c));
    return d;
}

// ---------------- cp.async helpers ----------------
__device__ __forceinline__ void cp16(void* smem_dst, const void* gsrc) {
    unsigned s = (unsigned)__cvta_generic_to_shared(smem_dst);
    asm volatile("cp.async.cg.shared.global [%0], [%1], 16;\n" :: "r"(s), "l"(gsrc));
}
__device__ __forceinline__ void cp_commit_wait_all() {
    asm volatile("cp.async.commit_group;\n" ::);
    asm volatile("cp.async.wait_group 0;\n" ::);
}

// ---------------- kernel 1: per-row dedup (sorted unique pids) -------------
// dtype detect fused: reads 128 int64 words (in-bounds for both layouts);
// int32 data read as int64 yields values >= 2^32 -> all-valid => int64.
__global__ void dedup_kernel(const void* idx_raw) {
    const int b = blockIdx.x;
    const int t = threadIdx.x;
    __shared__ int pids[K_CAND];
    __shared__ int wsum[8];
    __shared__ int s_ok;

    if (t == 0) s_ok = 1;
    __syncthreads();
    if (t < 128) {
        long long v = ((const long long*)idx_raw)[b * 128 + t];
        if (v < 0 || v >= (long long)N_EMB) atomicAnd(&s_ok, 0);
    }
    __syncthreads();
    const int is64 = s_ok;

    long long v;
    if (is64) v = ((const long long*)idx_raw)[b * K_CAND + t];
    else      v = (long long)(((const int*)idx_raw)[b * K_CAND + t]);
    pids[t] = (int)(v >> 7);   // emb2pid[i] == i / DOC_LEN, DOC_LEN = 128
    __syncthreads();

    // bitonic sort ascending (256 elements, 256 threads)
    for (int k = 2; k <= K_CAND; k <<= 1) {
        for (int j = k >> 1; j > 0; j >>= 1) {
            int ixj = t ^ j;
            if (ixj > t) {
                int a = pids[t], c = pids[ixj];
                bool up = ((t & k) == 0);
                if ((a > c) == up) { pids[t] = c; pids[ixj] = a; }
            }
            __syncthreads();
        }
    }

    int myv  = pids[t];
    int flag = (t == 0) || (myv != pids[t - 1]);

    unsigned mask = __ballot_sync(0xffffffffu, flag);
    int lane = t & 31, w = t >> 5;
    int pre  = __popc(mask & ((1u << lane) - 1));
    if (lane == 31) wsum[w] = pre + flag;
    __syncthreads();
    int base = 0;
    for (int i = 0; i < w; i++) base += wsum[i];
    int pos = base + pre;
    if (flag) g_upids[b * K_CAND + pos] = myv;
    if (t == K_CAND - 1) g_ucnt[b] = pos + flag;
}

// ---------------- kernel 2: scoring ----------------
// One CTA per (batch, candidate slot). 128 threads, 3 CTAs/SM.
// All inner-loop operands are loaded as 64-bit lanes (ulonglong2), so
// fma.rn.f32x2 consumes register pairs directly -- NO pack MOVs in the loop.
__global__ void __launch_bounds__(128, 3)
score_kernel(const float* __restrict__ qv, const float* __restrict__ vectors) {
    extern __shared__ float ds[];            // [DOC_LEN][DPITCH]
    __shared__ float wq[4];

    const int b    = blockIdx.y;
    const int slot = blockIdx.x;
    const int tid  = threadIdx.x;
    const int cnt  = g_ucnt[b];

    if (slot >= cnt) {
        if (tid == 0) g_scores[b * K_CAND + slot] = -CUDART_INF_F;
        return;
    }
    const int pid = g_upids[b * K_CAND + slot];

    // stage doc tile [128x128] (64 KB) via cp.async into pitch-132 smem
    const float4* d4 = (const float4*)(vectors + (size_t)pid * DOC_LEN * HID);
#pragma unroll
    for (int r = 0; r < 32; r++) {
        int i  = r * 128 + tid;
        int d  = i >> 5;                 // 32 float4 per row
        int h4 = i & 31;
        cp16(ds + d * DPITCH + h4 * 4, d4 + i);
    }
    cp_commit_wait_all();
    __syncthreads();

    const int qg = tid >> 5;     // warp id -> q group (8 rows)
    const int dg = tid & 31;     // lane    -> d base
    const float* qb = qv + (size_t)b * Q_LEN * HID + (qg * 8) * HID;

    u64 acc[8][4];
#pragma unroll
    for (int j = 0; j < 8; j++)
#pragma unroll
        for (int m = 0; m < 4; m++) acc[j][m] = 0ull;

#pragma unroll 4
    for (int k = 0; k < HID; k += 4) {
        u64 qA[8], qB[8];
#pragma unroll
        for (int j = 0; j < 8; j++) {
            ulonglong2 v = __ldg((const ulonglong2*)(qb + j * HID + k)); // uniform
            qA[j] = v.x;
            qB[j] = v.y;
        }
        u64 dA[4], dB[4];
#pragma unroll
        for (int m = 0; m < 4; m++) {
            ulonglong2 v = *(const ulonglong2*)(ds + (dg + 32 * m) * DPITCH + k);
            dA[m] = v.x;
            dB[m] = v.y;
        }
#pragma unroll
        for (int j = 0; j < 8; j++)
#pragma unroll
            for (int m = 0; m < 4; m++) {
                acc[j][m] = ffma2(dA[m], qA[j], acc[j][m]);
                acc[j][m] = ffma2(dB[m], qB[j], acc[j][m]);
            }
    }

    // per-q max over this thread's 4 d, then over the warp's 128 d
    float sum8 = 0.0f;
#pragma unroll
    for (int j = 0; j < 8; j++) {
        float mx = -CUDART_INF_F;
#pragma unroll
        for (int m = 0; m < 4; m++) {
            float2 f = f2unpack(acc[j][m]);
            mx = fmaxf(mx, f.x + f.y);
        }
#pragma unroll
        for (int o = 16; o > 0; o >>= 1)
            mx = fmaxf(mx, __shfl_xor_sync(0xffffffffu, mx, o));
        sum8 += mx;
    }
    if (dg == 0) wq[qg] = sum8;
    __syncthreads();
    if (tid == 0)
        g_scores[b * K_CAND + slot] =
            (wq[0] + wq[1] + wq[2] + wq[3]) * (1.0f / (float)Q_LEN);
}

// ---------------- kernel 3: warp-per-batch top-16 (shuffle-only) -----------
__global__ void topk_kernel(float* __restrict__ out, int out_size) {
    const int b    = blockIdx.x;
    const int lane = threadIdx.x;   // 32 threads

    float v[8];
    int   sl[8];
#pragma unroll
    for (int i = 0; i < 8; i++) {
        int s = i * 32 + lane;                      // coalesced
        v[i]  = g_scores[b * K_CAND + s];
        sl[i] = s;
    }
    const bool both = (out_size >= BATCH * K_OUT * 2);

    for (int it = 0; it < K_OUT; it++) {
        float bv = -CUDART_INF_F;
        int   bs = 1 << 30;
#pragma unroll
        for (int i = 0; i < 8; i++)
            if (v[i] > bv || (v[i] == bv && sl[i] < bs)) { bv = v[i]; bs = sl[i]; }
#pragma unroll
        for (int o = 16; o > 0; o >>= 1) {
            float ov = __shfl_xor_sync(0xffffffffu, bv, o);
            int   os = __shfl_xor_sync(0xffffffffu, bs, o);
            if (ov > bv || (ov == bv && os < bs)) { bv = ov; bs = os; }
        }
        if (lane == 0) {
            out[b * K_OUT + it] = (float)g_upids[b * K_CAND + bs];
            if (both) out[BATCH * K_OUT + b * K_OUT + it] = bv;
        }
        if ((bs & 31) == lane) v[bs >> 5] = -CUDART_INF_F;  // invalidate winner
    }
}

// ---------------- launcher ----------------
extern "C" void kernel_launch(void* const* d_in, const int* in_sizes, int n_in,
                              void* d_out, int out_size) {
    int qi = 0, ii = 1, vi = 3;
    for (int i = 0; i < n_in; i++) {
        if (in_sizes[i] == BATCH * Q_LEN * HID)            qi = i;
        else if (in_sizes[i] == BATCH * K_CAND)            ii = i;
        else if (in_sizes[i] == N_PIDS * DOC_LEN * HID)    vi = i;
    }
    const float* q       = (const float*)d_in[qi];
    const void*  idx     = d_in[ii];
    const float* vectors = (const float*)d_in[vi];

    dedup_kernel<<<BATCH, K_CAND>>>(idx);

    size_t smem = (size_t)(DOC_LEN * DPITCH) * sizeof(float);   // 67,584 B
    cudaFuncSetAttribute(score_kernel,
                         cudaFuncAttributeMaxDynamicSharedMemorySize, (int)smem);
    dim3 grid(K_CAND, BATCH);
    score_kernel<<<grid, 128, smem>>>(q, vectors);

    topk_kernel<<<BATCH, 32>>>((float*)d_out, out_size);
}

// round 5
// speedup vs baseline: 2.0222x; 1.3472x over previous
#include <cuda_runtime.h>
#include <cuda_bf16.h>
#include <math_constants.h>

// ---------------- problem constants ----------------
#define BATCH   32
#define Q_LEN   32
#define HID     128
#define DOC_LEN 128
#define K_CAND  256
#define K_OUT   16
#define N_PIDS  20000
#define N_EMB   (N_PIDS * DOC_LEN)

#define DPITCH  132   // doc smem pitch (floats): conflict-free LDSM + cp.async

typedef unsigned long long u64;
typedef unsigned int u32;

// ---------------- device scratch ----------------
__device__ int    g_upids[BATCH * K_CAND];
__device__ int    g_ucnt[BATCH];
__device__ float  g_scores[BATCH * K_CAND];
// q pre-packed into per-lane mma B fragments: [b][s=16][t=4][lane=32] float2
__device__ float2 g_qfrag[BATCH * 16 * 4 * 32];

// ---------------- helpers ----------------
__device__ __forceinline__ u32 tf32_rna(float x) {
    u32 r; asm("cvt.rna.tf32.f32 %0, %1;" : "=r"(r) : "f"(x));
    return r;
}
__device__ __forceinline__ void split_tf32(float x, u32& hi, u32& lo) {
    hi = tf32_rna(x);
    lo = tf32_rna(x - __uint_as_float(hi));
}
__device__ __forceinline__ void cp16(void* smem_dst, const void* gsrc) {
    u32 s = (u32)__cvta_generic_to_shared(smem_dst);
    asm volatile("cp.async.cg.shared.global [%0], [%1], 16;\n" :: "r"(s), "l"(gsrc));
}
// mma.sync m16n8k8 tf32 (baseline sm_80+ feature; NOT arch-specific)
__device__ __forceinline__ void mma8(float* c, const u32* a, const u32* b) {
    asm volatile(
        "mma.sync.aligned.m16n8k8.row.col.f32.tf32.tf32.f32 "
        "{%0,%1,%2,%3}, {%4,%5,%6,%7}, {%8,%9}, {%0,%1,%2,%3};"
        : "+f"(c[0]), "+f"(c[1]), "+f"(c[2]), "+f"(c[3])
        : "r"(a[0]), "r"(a[1]), "r"(a[2]), "r"(a[3]), "r"(b[0]), "r"(b[1]));
}

// ---------------- kernel 0: pack q into B fragments ------------------------
// b0(lane) = q[8t + (lane>>2)][8s + (lane&3)], b1 = same with k+4.
__global__ void qprep_kernel(const float* __restrict__ qv) {
    const int b = blockIdx.x;
    const int tid = threadIdx.x;
    const float* src = qv + (size_t)b * Q_LEN * HID;
    float2* dst = g_qfrag + (size_t)b * (16 * 4 * 32);
    for (int idx = tid; idx < 16 * 4 * 32; idx += 128) {
        int s = idx >> 7;
        int t = (idx >> 5) & 3;
        int l = idx & 31;
        int n = 8 * t + (l >> 2);
        int k = 8 * s + (l & 3);
        float2 v;
        v.x = src[n * HID + k];
        v.y = src[n * HID + k + 4];
        dst[idx] = v;
    }
}

// ---------------- kernel 1: per-row dedup (sorted unique pids) ------------
__global__ void dedup_kernel(const void* idx_raw) {
    const int b = blockIdx.x;
    const int t = threadIdx.x;
    __shared__ int pids[K_CAND];
    __shared__ int wsum[8];
    __shared__ int s_ok;

    if (t == 0) s_ok = 1;
    __syncthreads();
    if (t < 128) {
        long long v = ((const long long*)idx_raw)[b * 128 + t];
        if (v < 0 || v >= (long long)N_EMB) atomicAnd(&s_ok, 0);
    }
    __syncthreads();
    const int is64 = s_ok;

    long long v;
    if (is64) v = ((const long long*)idx_raw)[b * K_CAND + t];
    else      v = (long long)(((const int*)idx_raw)[b * K_CAND + t]);
    pids[t] = (int)(v >> 7);   // emb2pid[i] == i / 128
    __syncthreads();

    for (int k = 2; k <= K_CAND; k <<= 1) {
        for (int j = k >> 1; j > 0; j >>= 1) {
            int ixj = t ^ j;
            if (ixj > t) {
                int a = pids[t], c = pids[ixj];
                bool up = ((t & k) == 0);
                if ((a > c) == up) { pids[t] = c; pids[ixj] = a; }
            }
            __syncthreads();
        }
    }

    int myv  = pids[t];
    int flag = (t == 0) || (myv != pids[t - 1]);
    unsigned mask = __ballot_sync(0xffffffffu, flag);
    int lane = t & 31, w = t >> 5;
    int pre  = __popc(mask & ((1u << lane) - 1));
    if (lane == 31) wsum[w] = pre + flag;
    __syncthreads();
    int base = 0;
    for (int i = 0; i < w; i++) base += wsum[i];
    int pos = base + pre;
    if (flag) g_upids[b * K_CAND + pos] = myv;
    if (t == K_CAND - 1) g_ucnt[b] = pos + flag;
}

// ---------------- kernel 2: 3xTF32 mma.sync scoring -------------------------
// One CTA per (b, slot), 128 threads. Warp w: docs [32w, 32w+32) x all 32 q.
// A (docs) via ldmatrix.x4 from smem; B (q) via prepacked LDG.64 fragments.
__global__ void __launch_bounds__(128, 3)
score_kernel(const float* __restrict__ vectors) {
    extern __shared__ float ds[];            // [DOC_LEN][DPITCH]
    __shared__ float red[4 * 32];

    const int b    = blockIdx.y;
    const int slot = blockIdx.x;
    const int tid  = threadIdx.x;
    const int wid  = tid >> 5;
    const int lane = tid & 31;

    if (slot >= g_ucnt[b]) {
        if (tid == 0) g_scores[b * K_CAND + slot] = -CUDART_INF_F;
        return;
    }
    const int pid = g_upids[b * K_CAND + slot];

    // stage doc tile [128x128] via cp.async
    const float4* d4 = (const float4*)(vectors + (size_t)pid * DOC_LEN * HID);
#pragma unroll
    for (int r = 0; r < 32; r++) {
        int i  = r * 128 + tid;
        int d  = i >> 5;
        int h4 = i & 31;
        cp16(ds + d * DPITCH + h4 * 4, d4 + i);
    }
    asm volatile("cp.async.commit_group;\n" ::);
    asm volatile("cp.async.wait_group 0;\n" ::);
    __syncthreads();

    // ldmatrix lane addressing (per m-tile): mat = lane>>3
    const int mat     = lane >> 3;
    const int row_off = (mat & 1) * 8 + (lane & 7);
    const int col_off = (mat >> 1) * 4;
    const u32 ds_base = (u32)__cvta_generic_to_shared(ds);

    const float2* qf = g_qfrag + (size_t)b * (16 * 4 * 32) + lane;

    float acc[2][4][4];
#pragma unroll
    for (int mt = 0; mt < 2; mt++)
#pragma unroll
        for (int t = 0; t < 4; t++)
#pragma unroll
            for (int r = 0; r < 4; r++) acc[mt][t][r] = 0.0f;

#pragma unroll 4
    for (int s = 0; s < 16; s++) {
        u32 ahi[2][4], alo[2][4];
#pragma unroll
        for (int mt = 0; mt < 2; mt++) {
            int m0 = wid * 32 + mt * 16;
            u32 addr = ds_base + (u32)(((m0 + row_off) * DPITCH + 8 * s + col_off) * 4);
            u32 r0, r1, r2, r3;
            asm volatile(
                "ldmatrix.sync.aligned.m8n8.x4.shared.b16 {%0,%1,%2,%3}, [%4];"
                : "=r"(r0), "=r"(r1), "=r"(r2), "=r"(r3) : "r"(addr));
            split_tf32(__uint_as_float(r0), ahi[mt][0], alo[mt][0]);
            split_tf32(__uint_as_float(r1), ahi[mt][1], alo[mt][1]);
            split_tf32(__uint_as_float(r2), ahi[mt][2], alo[mt][2]);
            split_tf32(__uint_as_float(r3), ahi[mt][3], alo[mt][3]);
        }
#pragma unroll
        for (int t = 0; t < 4; t++) {
            float2 v = __ldg(&qf[(s * 4 + t) * 32]);
            u32 bh[2], bl[2];
            split_tf32(v.x, bh[0], bl[0]);
            split_tf32(v.y, bh[1], bl[1]);
#pragma unroll
            for (int mt = 0; mt < 2; mt++) {
                mma8(acc[mt][t], ahi[mt], bh);   // hi*hi
                mma8(acc[mt][t], ahi[mt], bl);   // hi*lo
                mma8(acc[mt][t], alo[mt], bh);   // lo*hi
            }
        }
    }

    // epilogue: per-q max over this warp's 32 docs
    // C frag: c0(row gid, col 2c), c1(+1), c2(row gid+8, col 2c), c3(+1)
#pragma unroll
    for (int t = 0; t < 4; t++) {
        float mx0 = fmaxf(fmaxf(acc[0][t][0], acc[0][t][2]),
                          fmaxf(acc[1][t][0], acc[1][t][2]));
        float mx1 = fmaxf(fmaxf(acc[0][t][1], acc[0][t][3]),
                          fmaxf(acc[1][t][1], acc[1][t][3]));
#pragma unroll
        for (int o = 4; o <= 16; o <<= 1) {
            mx0 = fmaxf(mx0, __shfl_xor_sync(0xffffffffu, mx0, o));
            mx1 = fmaxf(mx1, __shfl_xor_sync(0xffffffffu, mx1, o));
        }
        if (lane < 4) {
            red[wid * 32 + 8 * t + 2 * lane + 0] = mx0;
            red[wid * 32 + 8 * t + 2 * lane + 1] = mx1;
        }
    }
    __syncthreads();

    if (wid == 0) {
        float m = fmaxf(fmaxf(red[lane], red[32 + lane]),
                        fmaxf(red[64 + lane], red[96 + lane]));
#pragma unroll
        for (int o = 16; o > 0; o >>= 1)
            m += __shfl_xor_sync(0xffffffffu, m, o);
        if (lane == 0)
            g_scores[b * K_CAND + slot] = m * (1.0f / (float)Q_LEN);
    }
}

// ---------------- kernel 3: warp-per-batch top-16 --------------------------
__global__ void topk_kernel(float* __restrict__ out, int out_size) {
    const int b    = blockIdx.x;
    const int lane = threadIdx.x;
    float v[8]; int sl[8];
#pragma unroll
    for (int i = 0; i < 8; i++) {
        int s = i * 32 + lane;
        v[i] = g_scores[b * K_CAND + s];
        sl[i] = s;
    }
    const bool both = (out_size >= BATCH * K_OUT * 2);
    for (int it = 0; it < K_OUT; it++) {
        float bv = -CUDART_INF_F; int bs = 1 << 30;
#pragma unroll
        for (int i = 0; i < 8; i++)
            if (v[i] > bv || (v[i] == bv && sl[i] < bs)) { bv = v[i]; bs = sl[i]; }
#pragma unroll
        for (int o = 16; o > 0; o >>= 1) {
            float ov = __shfl_xor_sync(0xffffffffu, bv, o);
            int   os = __shfl_xor_sync(0xffffffffu, bs, o);
            if (ov > bv || (ov == bv && os < bs)) { bv = ov; bs = os; }
        }
        if (lane == 0) {
            out[b * K_OUT + it] = (float)g_upids[b * K_CAND + bs];
            if (both) out[BATCH * K_OUT + b * K_OUT + it] = bv;
        }
        if ((bs & 31) == lane) v[bs >> 5] = -CUDART_INF_F;
    }
}

// ---------------- launcher ----------------
extern "C" void kernel_launch(void* const* d_in, const int* in_sizes, int n_in,
                              void* d_out, int out_size) {
    int qi = 0, ii = 1, vi = 3;
    for (int i = 0; i < n_in; i++) {
        if (in_sizes[i] == BATCH * Q_LEN * HID)            qi = i;
        else if (in_sizes[i] == BATCH * K_CAND)            ii = i;
        else if (in_sizes[i] == N_PIDS * DOC_LEN * HID)    vi = i;
    }
    const float* q       = (const float*)d_in[qi];
    const void*  idx     = d_in[ii];
    const float* vectors = (const float*)d_in[vi];

    qprep_kernel<<<BATCH, 128>>>(q);
    dedup_kernel<<<BATCH, K_CAND>>>(idx);

    size_t smem = (size_t)(DOC_LEN * DPITCH) * sizeof(float);   // 67,584 B
    cudaFuncSetAttribute(score_kernel,
                         cudaFuncAttributeMaxDynamicSharedMemorySize, (int)smem);
    dim3 grid(K_CAND, BATCH);
    score_kernel<<<grid, 128, smem>>>(vectors);

    topk_kernel<<<BATCH, 32>>>((float*)d_out, out_size);
}

// round 6
// speedup vs baseline: 2.5327x; 1.2524x over previous
#include <cuda_runtime.h>
#include <cuda_bf16.h>
#include <math_constants.h>

// ---------------- problem constants ----------------
#define BATCH   32
#define Q_LEN   32
#define HID     128
#define DOC_LEN 128
#define K_CAND  256
#define K_OUT   16
#define N_PIDS  20000
#define N_EMB   (N_PIDS * DOC_LEN)

#define DPITCH  132   // doc smem pitch (floats): conflict-free LDSM + cp.async

typedef unsigned long long u64;
typedef unsigned int u32;

// ---------------- device scratch ----------------
__device__ int    g_upids[BATCH * K_CAND];
__device__ int    g_ucnt[BATCH];
__device__ float  g_scores[BATCH * K_CAND];
// q pre-split B fragments: [b][s=16][t=4][lane=32] -> uint2 (k, k+4), hi & lo
__device__ uint2  g_qfh[BATCH * 16 * 4 * 32];
__device__ uint2  g_qfl[BATCH * 16 * 4 * 32];

// ---------------- helpers ----------------
__device__ __forceinline__ u32 tf32_rna(float x) {
    u32 r; asm("cvt.rna.tf32.f32 %0, %1;" : "=r"(r) : "f"(x));
    return r;
}
__device__ __forceinline__ void split_tf32(float x, u32& hi, u32& lo) {
    hi = tf32_rna(x);
    lo = tf32_rna(x - __uint_as_float(hi));
}
__device__ __forceinline__ void cp16(void* smem_dst, const void* gsrc) {
    u32 s = (u32)__cvta_generic_to_shared(smem_dst);
    asm volatile("cp.async.cg.shared.global [%0], [%1], 16;\n" :: "r"(s), "l"(gsrc));
}
template <int N>
__device__ __forceinline__ void cp_wait() {
    asm volatile("cp.async.wait_group %0;\n" :: "n"(N));
}
__device__ __forceinline__ void mma8(float* c, const u32* a, const u32* b) {
    asm volatile(
        "mma.sync.aligned.m16n8k8.row.col.f32.tf32.tf32.f32 "
        "{%0,%1,%2,%3}, {%4,%5,%6,%7}, {%8,%9}, {%0,%1,%2,%3};"
        : "+f"(c[0]), "+f"(c[1]), "+f"(c[2]), "+f"(c[3])
        : "r"(a[0]), "r"(a[1]), "r"(a[2]), "r"(a[3]), "r"(b[0]), "r"(b[1]));
}
// monotone map: ascending u32 <=> ascending float (works for -inf)
__device__ __forceinline__ u32 fmap(float f) {
    u32 s = __float_as_uint(f);
    return (s & 0x80000000u) ? ~s : (s | 0x80000000u);
}

// ---------------- kernel 1: prep (dedup for bid<32, qprep for bid>=32) -----
__global__ void prep_kernel(const void* idx_raw, const float* __restrict__ qv) {
    const int role = blockIdx.x >> 5;
    const int b    = blockIdx.x & 31;
    const int t    = threadIdx.x;

    if (role == 1) {
        // ---- qprep: pack q into pre-split hi/lo B fragments ----
        const float* src = qv + (size_t)b * Q_LEN * HID;
        uint2* dh = g_qfh + (size_t)b * (16 * 4 * 32);
        uint2* dl = g_qfl + (size_t)b * (16 * 4 * 32);
        for (int idx = t; idx < 16 * 4 * 32; idx += 256) {
            int s = idx >> 7;
            int tt = (idx >> 5) & 3;
            int l = idx & 31;
            int n = 8 * tt + (l >> 2);
            int k = 8 * s + (l & 3);
            float x0 = src[n * HID + k];
            float x1 = src[n * HID + k + 4];
            uint2 h, lo;
            split_tf32(x0, h.x, lo.x);
            split_tf32(x1, h.y, lo.y);
            dh[idx] = h;
            dl[idx] = lo;
        }
        return;
    }

    // ---- dedup: sorted unique pids ----
    __shared__ int pids[K_CAND];
    __shared__ int wsum[8];
    __shared__ int s_ok;

    if (t == 0) s_ok = 1;
    __syncthreads();
    if (t < 128) {
        long long v = ((const long long*)idx_raw)[b * 128 + t];
        if (v < 0 || v >= (long long)N_EMB) atomicAnd(&s_ok, 0);
    }
    __syncthreads();
    const int is64 = s_ok;

    long long v;
    if (is64) v = ((const long long*)idx_raw)[b * K_CAND + t];
    else      v = (long long)(((const int*)idx_raw)[b * K_CAND + t]);
    pids[t] = (int)(v >> 7);   // emb2pid[i] == i / 128
    __syncthreads();

    for (int k = 2; k <= K_CAND; k <<= 1) {
        for (int j = k >> 1; j > 0; j >>= 1) {
            int ixj = t ^ j;
            if (ixj > t) {
                int a = pids[t], c = pids[ixj];
                bool up = ((t & k) == 0);
                if ((a > c) == up) { pids[t] = c; pids[ixj] = a; }
            }
            __syncthreads();
        }
    }

    int myv  = pids[t];
    int flag = (t == 0) || (myv != pids[t - 1]);
    unsigned mask = __ballot_sync(0xffffffffu, flag);
    int lane = t & 31, w = t >> 5;
    int pre  = __popc(mask & ((1u << lane) - 1));
    if (lane == 31) wsum[w] = pre + flag;
    __syncthreads();
    int base = 0;
    for (int i = 0; i < w; i++) base += wsum[i];
    int pos = base + pre;
    if (flag) g_upids[b * K_CAND + pos] = myv;
    if (t == K_CAND - 1) g_ucnt[b] = pos + flag;
}

// ---------------- kernel 2: 3xTF32 mma.sync scoring, K-chunk pipelined -----
// One CTA per (b, slot), 128 threads. Warp w: docs [32w, 32w+32) x all 32 q.
__global__ void __launch_bounds__(128, 3)
score_kernel(const float* __restrict__ vectors) {
    extern __shared__ float ds[];            // [DOC_LEN][DPITCH]
    __shared__ float red[4 * 32];

    const int b    = blockIdx.y;
    const int slot = blockIdx.x;
    const int tid  = threadIdx.x;
    const int wid  = tid >> 5;
    const int lane = tid & 31;

    if (slot >= g_ucnt[b]) {
        if (tid == 0) g_scores[b * K_CAND + slot] = -CUDART_INF_F;
        return;
    }
    const int pid = g_upids[b * K_CAND + slot];

    // stage doc tile in 4 K-chunks (columns 32c..32c+32), one commit group each
    const float* doc = vectors + (size_t)pid * DOC_LEN * HID;
#pragma unroll
    for (int c = 0; c < 4; c++) {
#pragma unroll
        for (int r = 0; r < 8; r++) {
            int i  = r * 128 + tid;          // 1024 cp16 per chunk
            int d  = i >> 3;                 // 8 x 16B per row-chunk
            int h4 = i & 7;
            cp16(ds + d * DPITCH + 32 * c + h4 * 4, doc + d * HID + 32 * c + h4 * 4);
        }
        asm volatile("cp.async.commit_group;\n" ::);
    }

    // ldmatrix lane addressing
    const int mat     = lane >> 3;
    const int row_off = (mat & 1) * 8 + (lane & 7);
    const int col_off = (mat >> 1) * 4;
    const u32 ds_base = (u32)__cvta_generic_to_shared(ds);

    const uint2* qfh = g_qfh + (size_t)b * (16 * 4 * 32) + lane;
    const uint2* qfl = g_qfl + (size_t)b * (16 * 4 * 32) + lane;

    float acc[2][4][4];
#pragma unroll
    for (int mt = 0; mt < 2; mt++)
#pragma unroll
        for (int t = 0; t < 4; t++)
#pragma unroll
            for (int r = 0; r < 4; r++) acc[mt][t][r] = 0.0f;

#pragma unroll
    for (int c = 0; c < 4; c++) {
        if (c == 0) cp_wait<3>();
        else if (c == 1) cp_wait<2>();
        else if (c == 2) cp_wait<1>();
        else cp_wait<0>();
        __syncthreads();

#pragma unroll
        for (int si = 0; si < 4; si++) {
            const int s = 4 * c + si;
            u32 ahi[2][4], alo[2][4];
#pragma unroll
            for (int mt = 0; mt < 2; mt++) {
                int m0 = wid * 32 + mt * 16;
                u32 addr = ds_base + (u32)(((m0 + row_off) * DPITCH + 8 * s + col_off) * 4);
                u32 r0, r1, r2, r3;
                asm volatile(
                    "ldmatrix.sync.aligned.m8n8.x4.shared.b16 {%0,%1,%2,%3}, [%4];"
                    : "=r"(r0), "=r"(r1), "=r"(r2), "=r"(r3) : "r"(addr));
                split_tf32(__uint_as_float(r0), ahi[mt][0], alo[mt][0]);
                split_tf32(__uint_as_float(r1), ahi[mt][1], alo[mt][1]);
                split_tf32(__uint_as_float(r2), ahi[mt][2], alo[mt][2]);
                split_tf32(__uint_as_float(r3), ahi[mt][3], alo[mt][3]);
            }
#pragma unroll
            for (int t = 0; t < 4; t++) {
                uint2 vh = __ldg(&qfh[(s * 4 + t) * 32]);
                uint2 vl = __ldg(&qfl[(s * 4 + t) * 32]);
                u32 bh[2] = { vh.x, vh.y };
                u32 bl[2] = { vl.x, vl.y };
#pragma unroll
                for (int mt = 0; mt < 2; mt++) {
                    mma8(acc[mt][t], ahi[mt], bh);   // hi*hi
                    mma8(acc[mt][t], ahi[mt], bl);   // hi*lo
                    mma8(acc[mt][t], alo[mt], bh);   // lo*hi
                }
            }
        }
    }

    // epilogue: per-q max over this warp's 32 docs
#pragma unroll
    for (int t = 0; t < 4; t++) {
        float mx0 = fmaxf(fmaxf(acc[0][t][0], acc[0][t][2]),
                          fmaxf(acc[1][t][0], acc[1][t][2]));
        float mx1 = fmaxf(fmaxf(acc[0][t][1], acc[0][t][3]),
                          fmaxf(acc[1][t][1], acc[1][t][3]));
#pragma unroll
        for (int o = 4; o <= 16; o <<= 1) {
            mx0 = fmaxf(mx0, __shfl_xor_sync(0xffffffffu, mx0, o));
            mx1 = fmaxf(mx1, __shfl_xor_sync(0xffffffffu, mx1, o));
        }
        if (lane < 4) {
            red[wid * 32 + 8 * t + 2 * lane + 0] = mx0;
            red[wid * 32 + 8 * t + 2 * lane + 1] = mx1;
        }
    }
    __syncthreads();

    if (wid == 0) {
        float m = fmaxf(fmaxf(red[lane], red[32 + lane]),
                        fmaxf(red[64 + lane], red[96 + lane]));
#pragma unroll
        for (int o = 16; o > 0; o >>= 1)
            m += __shfl_xor_sync(0xffffffffu, m, o);
        if (lane == 0)
            g_scores[b * K_CAND + slot] = m * (1.0f / (float)Q_LEN);
    }
}

// ---------------- kernel 3: bitonic-sort top-16 ----------------------------
// Key = (~fmap(score) << 32) | slot: ascending sort => descending score,
// ascending slot on ties (matches jax top_k / lower-index tiebreak).
__global__ void topk_kernel(float* __restrict__ out, int out_size) {
    const int b = blockIdx.x;
    const int t = threadIdx.x;    // 256
    __shared__ u64 keys[K_CAND];

    float sc = g_scores[b * K_CAND + t];
    keys[t] = ((u64)(~fmap(sc)) << 32) | (u32)t;
    __syncthreads();

    for (int k = 2; k <= K_CAND; k <<= 1) {
        for (int j = k >> 1; j > 0; j >>= 1) {
            int ixj = t ^ j;
            if (ixj > t) {
                u64 a = keys[t], c = keys[ixj];
                bool up = ((t & k) == 0);
                if ((a > c) == up) { keys[t] = c; keys[ixj] = a; }
            }
            __syncthreads();
        }
    }

    if (t < K_OUT) {
        int slotw = (int)(keys[t] & 0xffffffffu);
        out[b * K_OUT + t] = (float)g_upids[b * K_CAND + slotw];
        if (out_size >= BATCH * K_OUT * 2)
            out[BATCH * K_OUT + b * K_OUT + t] = g_scores[b * K_CAND + slotw];
    }
}

// ---------------- launcher ----------------
extern "C" void kernel_launch(void* const* d_in, const int* in_sizes, int n_in,
                              void* d_out, int out_size) {
    int qi = 0, ii = 1, vi = 3;
    for (int i = 0; i < n_in; i++) {
        if (in_sizes[i] == BATCH * Q_LEN * HID)            qi = i;
        else if (in_sizes[i] == BATCH * K_CAND)            ii = i;
        else if (in_sizes[i] == N_PIDS * DOC_LEN * HID)    vi = i;
    }
    const float* q       = (const float*)d_in[qi];
    const void*  idx     = d_in[ii];
    const float* vectors = (const float*)d_in[vi];

    prep_kernel<<<64, 256>>>(idx, q);

    size_t smem = (size_t)(DOC_LEN * DPITCH) * sizeof(float);   // 67,584 B
    cudaFuncSetAttribute(score_kernel,
                         cudaFuncAttributeMaxDynamicSharedMemorySize, (int)smem);
    dim3 grid(K_CAND, BATCH);
    score_kernel<<<grid, 128, smem>>>(vectors);

    topk_kernel<<<BATCH, K_CAND>>>((float*)d_out, out_size);
}

// round 7
// speedup vs baseline: 3.2745x; 1.2929x over previous
#include <cuda_runtime.h>
#include <cuda_fp16.h>
#include <math_constants.h>

// ---------------- problem constants ----------------
#define BATCH   32
#define Q_LEN   32
#define HID     128
#define DOC_LEN 128
#define K_CAND  256
#define K_OUT   16
#define N_PIDS  20000
#define N_EMB   (N_PIDS * DOC_LEN)

#define DPITCH  132   // doc smem pitch (floats): conflict-free LDS.64/cp.async

typedef unsigned long long u64;
typedef unsigned int u32;

// ---------------- device scratch ----------------
__device__ int    g_upids[BATCH * K_CAND];
__device__ int    g_ucnt[BATCH];
__device__ float  g_scores[BATCH * K_CAND];
// q pre-split fp16 B fragments: [b][s=8][t=4][lane=32] -> uint2 (b0,b1), hi & lo
__device__ uint2  g_qfh[BATCH * 8 * 4 * 32];
__device__ uint2  g_qfl[BATCH * 8 * 4 * 32];

// ---------------- helpers ----------------
__device__ __forceinline__ void split_h2(float2 v, u32& hi, u32& lo) {
    __half2 h = __float22half2_rn(v);                 // 1 cvt (packed)
    float2 hf = __half22float2(h);                    // 2 cvt
    __half2 l = __float22half2_rn(
        make_float2(v.x - hf.x, v.y - hf.y));         // 2 sub + 1 cvt
    hi = *reinterpret_cast<u32*>(&h);
    lo = *reinterpret_cast<u32*>(&l);
}
__device__ __forceinline__ void cp16(void* smem_dst, const void* gsrc) {
    u32 s = (u32)__cvta_generic_to_shared(smem_dst);
    asm volatile("cp.async.cg.shared.global [%0], [%1], 16;\n" :: "r"(s), "l"(gsrc));
}
template <int N>
__device__ __forceinline__ void cp_wait() {
    asm volatile("cp.async.wait_group %0;\n" :: "n"(N));
}
__device__ __forceinline__ void mma16(float* c, const u32* a, const u32* b) {
    asm volatile(
        "mma.sync.aligned.m16n8k16.row.col.f32.f16.f16.f32 "
        "{%0,%1,%2,%3}, {%4,%5,%6,%7}, {%8,%9}, {%0,%1,%2,%3};"
        : "+f"(c[0]), "+f"(c[1]), "+f"(c[2]), "+f"(c[3])
        : "r"(a[0]), "r"(a[1]), "r"(a[2]), "r"(a[3]), "r"(b[0]), "r"(b[1]));
}
// monotone map: ascending u32 <=> ascending float (works for -inf)
__device__ __forceinline__ u32 fmap(float f) {
    u32 s = __float_as_uint(f);
    return (s & 0x80000000u) ? ~s : (s | 0x80000000u);
}

// ---------------- kernel 1: prep (dedup for bid<32, qprep for bid>=32) -----
__global__ void prep_kernel(const void* idx_raw, const float* __restrict__ qv) {
    const int role = blockIdx.x >> 5;
    const int b    = blockIdx.x & 31;
    const int t    = threadIdx.x;

    if (role == 1) {
        // ---- qprep: pack q into pre-split fp16 hi/lo B fragments ----
        // m16n8k16 B frag: b0 = {(k0,n),(k0+1,n)}, b1 = {(k0+8,n),(k0+9,n)},
        // n = 8t + (lane>>2), k0 = 16s + 2*(lane&3).
        const float* src = qv + (size_t)b * Q_LEN * HID;
        uint2* dh = g_qfh + (size_t)b * (8 * 4 * 32);
        uint2* dl = g_qfl + (size_t)b * (8 * 4 * 32);
        for (int idx = t; idx < 8 * 4 * 32; idx += 256) {
            int s  = idx >> 7;
            int tt = (idx >> 5) & 3;
            int l  = idx & 31;
            int n  = 8 * tt + (l >> 2);
            int k0 = 16 * s + 2 * (l & 3);
            u32 b0h, b0l, b1h, b1l;
            split_h2(make_float2(src[n * HID + k0],     src[n * HID + k0 + 1]), b0h, b0l);
            split_h2(make_float2(src[n * HID + k0 + 8], src[n * HID + k0 + 9]), b1h, b1l);
            dh[idx] = make_uint2(b0h, b1h);
            dl[idx] = make_uint2(b0l, b1l);
        }
        return;
    }

    // ---- dedup: sorted unique pids ----
    __shared__ int pids[K_CAND];
    __shared__ int wsum[8];
    __shared__ int s_ok;

    if (t == 0) s_ok = 1;
    __syncthreads();
    if (t < 128) {
        long long v = ((const long long*)idx_raw)[b * 128 + t];
        if (v < 0 || v >= (long long)N_EMB) atomicAnd(&s_ok, 0);
    }
    __syncthreads();
    const int is64 = s_ok;

    long long v;
    if (is64) v = ((const long long*)idx_raw)[b * K_CAND + t];
    else      v = (long long)(((const int*)idx_raw)[b * K_CAND + t]);
    pids[t] = (int)(v >> 7);   // emb2pid[i] == i / 128
    __syncthreads();

    for (int k = 2; k <= K_CAND; k <<= 1) {
        for (int j = k >> 1; j > 0; j >>= 1) {
            int ixj = t ^ j;
            if (ixj > t) {
                int a = pids[t], c = pids[ixj];
                bool up = ((t & k) == 0);
                if ((a > c) == up) { pids[t] = c; pids[ixj] = a; }
            }
            __syncthreads();
        }
    }

    int myv  = pids[t];
    int flag = (t == 0) || (myv != pids[t - 1]);
    unsigned mask = __ballot_sync(0xffffffffu, flag);
    int lane = t & 31, w = t >> 5;
    int pre  = __popc(mask & ((1u << lane) - 1));
    if (lane == 31) wsum[w] = pre + flag;
    __syncthreads();
    int base = 0;
    for (int i = 0; i < w; i++) base += wsum[i];
    int pos = base + pre;
    if (flag) g_upids[b * K_CAND + pos] = myv;
    if (t == K_CAND - 1) g_ucnt[b] = pos + flag;
}

// ---------------- kernel 2: 3xFP16 m16n8k16 scoring, K-chunk pipelined -----
// One CTA per (b, slot), 128 threads. Warp w: docs [32w, 32w+32) x all 32 q.
// hi=fp16(x), lo=fp16(x-hi); hi*hi + hi*lo + lo*hi in fp32-accum MMA
// (same 11-bit mantissa as tf32 -> ~1e-6 error, half the MMA instructions).
__global__ void __launch_bounds__(128, 3)
score_kernel(const float* __restrict__ vectors) {
    extern __shared__ float ds[];            // [DOC_LEN][DPITCH]
    __shared__ float red[4 * 32];

    const int b    = blockIdx.y;
    const int slot = blockIdx.x;
    const int tid  = threadIdx.x;
    const int wid  = tid >> 5;
    const int lane = tid & 31;

    if (slot >= g_ucnt[b]) {
        if (tid == 0) g_scores[b * K_CAND + slot] = -CUDART_INF_F;
        return;
    }
    const int pid = g_upids[b * K_CAND + slot];

    // stage doc tile in 4 K-chunks (columns 32c..32c+32), one commit group each
    const float* doc = vectors + (size_t)pid * DOC_LEN * HID;
#pragma unroll
    for (int c = 0; c < 4; c++) {
#pragma unroll
        for (int r = 0; r < 8; r++) {
            int i  = r * 128 + tid;          // 1024 cp16 per chunk
            int d  = i >> 3;                 // 8 x 16B per row-chunk
            int h4 = i & 7;
            cp16(ds + d * DPITCH + 32 * c + h4 * 4, doc + d * HID + 32 * c + h4 * 4);
        }
        asm volatile("cp.async.commit_group;\n" ::);
    }

    const int arow = lane >> 2;          // 0..7
    const int acol = 2 * (lane & 3);     // 0,2,4,6
    const uint2* qfh = g_qfh + (size_t)b * (8 * 4 * 32) + lane;
    const uint2* qfl = g_qfl + (size_t)b * (8 * 4 * 32) + lane;

    float acc[2][4][4];
#pragma unroll
    for (int mt = 0; mt < 2; mt++)
#pragma unroll
        for (int t = 0; t < 4; t++)
#pragma unroll
            for (int r = 0; r < 4; r++) acc[mt][t][r] = 0.0f;

#pragma unroll
    for (int c = 0; c < 4; c++) {
        if (c == 0) cp_wait<3>();
        else if (c == 1) cp_wait<2>();
        else if (c == 2) cp_wait<1>();
        else cp_wait<0>();
        __syncthreads();

#pragma unroll
        for (int si = 0; si < 2; si++) {
            const int s = 2 * c + si;           // k16 step 0..7
            const float* kb = ds + 16 * s + acol;

            u32 ahi[2][4], alo[2][4];
#pragma unroll
            for (int mt = 0; mt < 2; mt++) {
                int m0 = wid * 32 + mt * 16 + arow;
                float2 f0 = *(const float2*)(kb + m0 * DPITCH);
                float2 f1 = *(const float2*)(kb + (m0 + 8) * DPITCH);
                float2 f2 = *(const float2*)(kb + 8 + m0 * DPITCH);
                float2 f3 = *(const float2*)(kb + 8 + (m0 + 8) * DPITCH);
                split_h2(f0, ahi[mt][0], alo[mt][0]);
                split_h2(f1, ahi[mt][1], alo[mt][1]);
                split_h2(f2, ahi[mt][2], alo[mt][2]);
                split_h2(f3, ahi[mt][3], alo[mt][3]);
            }
#pragma unroll
            for (int t = 0; t < 4; t++) {
                uint2 vh = __ldg(&qfh[(s * 4 + t) * 32]);
                uint2 vl = __ldg(&qfl[(s * 4 + t) * 32]);
                u32 bh[2] = { vh.x, vh.y };
                u32 bl[2] = { vl.x, vl.y };
#pragma unroll
                for (int mt = 0; mt < 2; mt++) {
                    mma16(acc[mt][t], ahi[mt], bh);   // hi*hi
                    mma16(acc[mt][t], ahi[mt], bl);   // hi*lo
                    mma16(acc[mt][t], alo[mt], bh);   // lo*hi
                }
            }
        }
    }

    // epilogue: per-q max over this warp's 32 docs
    // C frag: c0(row g, col 2c), c1(+1), c2(row g+8, col 2c), c3(+1)
#pragma unroll
    for (int t = 0; t < 4; t++) {
        float mx0 = fmaxf(acc[0][t][0], acc[0][t][2]);
        mx0 = fmaxf(mx0, fmaxf(acc[1][t][0], acc[1][t][2]));
        float mx1 = fmaxf(acc[0][t][1], acc[0][t][3]);
        mx1 = fmaxf(mx1, fmaxf(acc[1][t][1], acc[1][t][3]));
#pragma unroll
        for (int o = 4; o <= 16; o <<= 1) {
            mx0 = fmaxf(mx0, __shfl_xor_sync(0xffffffffu, mx0, o));
            mx1 = fmaxf(mx1, __shfl_xor_sync(0xffffffffu, mx1, o));
        }
        if (lane < 4) {
            red[wid * 32 + 8 * t + 2 * lane + 0] = mx0;
            red[wid * 32 + 8 * t + 2 * lane + 1] = mx1;
        }
    }
    __syncthreads();

    if (wid == 0) {
        float m = fmaxf(fmaxf(red[lane], red[32 + lane]),
                        fmaxf(red[64 + lane], red[96 + lane]));
#pragma unroll
        for (int o = 16; o > 0; o >>= 1)
            m += __shfl_xor_sync(0xffffffffu, m, o);
        if (lane == 0)
            g_scores[b * K_CAND + slot] = m * (1.0f / (float)Q_LEN);
    }
}

// ---------------- kernel 3: bitonic-sort top-16 ----------------------------
// Key = (~fmap(score) << 32) | slot: ascending sort => descending score,
// ascending slot on ties (matches jax top_k / lower-index tiebreak).
__global__ void topk_kernel(float* __restrict__ out, int out_size) {
    const int b = blockIdx.x;
    const int t = threadIdx.x;    // 256
    __shared__ u64 keys[K_CAND];

    float sc = g_scores[b * K_CAND + t];
    keys[t] = ((u64)(~fmap(sc)) << 32) | (u32)t;
    __syncthreads();

    for (int k = 2; k <= K_CAND; k <<= 1) {
        for (int j = k >> 1; j > 0; j >>= 1) {
            int ixj = t ^ j;
            if (ixj > t) {
                u64 a = keys[t], c = keys[ixj];
                bool up = ((t & k) == 0);
                if ((a > c) == up) { keys[t] = c; keys[ixj] = a; }
            }
            __syncthreads();
        }
    }

    if (t < K_OUT) {
        int slotw = (int)(keys[t] & 0xffffffffu);
        out[b * K_OUT + t] = (float)g_upids[b * K_CAND + slotw];
        if (out_size >= BATCH * K_OUT * 2)
            out[BATCH * K_OUT + b * K_OUT + t] = g_scores[b * K_CAND + slotw];
    }
}

// ---------------- launcher ----------------
extern "C" void kernel_launch(void* const* d_in, const int* in_sizes, int n_in,
                              void* d_out, int out_size) {
    int qi = 0, ii = 1, vi = 3;
    for (int i = 0; i < n_in; i++) {
        if (in_sizes[i] == BATCH * Q_LEN * HID)            qi = i;
        else if (in_sizes[i] == BATCH * K_CAND)            ii = i;
        else if (in_sizes[i] == N_PIDS * DOC_LEN * HID)    vi = i;
    }
    const float* q       = (const float*)d_in[qi];
    const void*  idx     = d_in[ii];
    const float* vectors = (const float*)d_in[vi];

    prep_kernel<<<64, 256>>>(idx, q);

    size_t smem = (size_t)(DOC_LEN * DPITCH) * sizeof(float);   // 67,584 B
    cudaFuncSetAttribute(score_kernel,
                         cudaFuncAttributeMaxDynamicSharedMemorySize, (int)smem);
    dim3 grid(K_CAND, BATCH);
    score_kernel<<<grid, 128, smem>>>(vectors);

    topk_kernel<<<BATCH, K_CAND>>>((float*)d_out, out_size);
}